// round 11
// baseline (speedup 1.0000x reference)
#include <cuda_runtime.h>
#include <cuda_fp16.h>
#include <cstdint>

#define TOK 8192
#define HD  2048
#define ID  1408
#define NE  8

#define BM   128
#define BK   64
#define BN1  128
#define BN2  256
#define NT1  (ID / BN1)   // 11
#define NT2  (HD / BN2)   // 8
#define NTHR 384          // 256 consumer + 128 producer
#define NSTG 4
#define KT1  (HD / BK)    // 32
#define KT2  (ID / BK)    // 22
#define A_ST 72           // 64 + 8 halves -> 144B row stride
#define B_ST 72           // B now [n][k] rows, same stride

// ---------------- device scratch (no allocations allowed) ----------------------
__device__ __half g_xh[(size_t)TOK * HD];       // fp16 x, [T][H]
__device__ __half g_wgT[(size_t)NE * ID * HD];  // fp16, TRANSPOSED [e][I][H]
__device__ __half g_wuT[(size_t)NE * ID * HD];  // [e][I][H]
__device__ __half g_wdT[(size_t)NE * HD * ID];  // [e][H][I]
__device__ int    g_cnt[NE];
__device__ int    g_tokp[NE * TOK];             // token | (k<<31)
__device__ float  g_w2[TOK * 2];                // per-token (w0, w1)
__device__ __half g_hh[(size_t)NE * TOK * ID];  // fp16 intermediate (slot-indexed)
__device__ float  g_y[(size_t)2 * TOK * HD];    // unweighted expert outputs per k

// ---------------- helpers ------------------------------------------------------
__device__ __forceinline__ uint32_t saddr(const void* p) {
    return (uint32_t)__cvta_generic_to_shared(p);
}
__device__ __forceinline__ void cp16(uint32_t dst, const void* src) {
    asm volatile("cp.async.cg.shared.global [%0], [%1], 16;" :: "r"(dst), "l"(src));
}
__device__ __forceinline__ void cp_commit() { asm volatile("cp.async.commit_group;"); }
template <int N>
__device__ __forceinline__ void cp_wait() { asm volatile("cp.async.wait_group %0;" :: "n"(N)); }

__device__ __forceinline__ void bar_sync(int id) {
    asm volatile("bar.sync %0, %1;" :: "r"(id), "n"(NTHR) : "memory");
}
__device__ __forceinline__ void bar_arrive(int id) {
    asm volatile("bar.arrive %0, %1;" :: "r"(id), "n"(NTHR) : "memory");
}

__device__ __forceinline__ void ldsm_x4(uint32_t* r, uint32_t addr) {
    asm volatile("ldmatrix.sync.aligned.m8n8.x4.shared.b16 {%0,%1,%2,%3}, [%4];"
                 : "=r"(r[0]), "=r"(r[1]), "=r"(r[2]), "=r"(r[3]) : "r"(addr));
}
__device__ __forceinline__ void mma_f16(float d[4], const uint32_t a[4], const uint32_t b[2]) {
    asm volatile(
        "mma.sync.aligned.m16n8k16.row.col.f32.f16.f16.f32 "
        "{%0,%1,%2,%3}, {%4,%5,%6,%7}, {%8,%9}, {%0,%1,%2,%3};"
        : "+f"(d[0]), "+f"(d[1]), "+f"(d[2]), "+f"(d[3])
        : "r"(a[0]), "r"(a[1]), "r"(a[2]), "r"(a[3]), "r"(b[0]), "r"(b[1]));
}

// ---------------- tile scheduler -------------------------------------------------
__device__ __forceinline__ int total_tiles(int NT) {
    int T = 0;
#pragma unroll
    for (int ee = 0; ee < NE; ee++) T += ((g_cnt[ee] + BM - 1) / BM) * NT;
    return T;
}
__device__ __forceinline__ void decode_tile(int tile, int NT, int& e_o, int& mb_o,
                                            int& nb_idx_o, int& cnt_o) {
    int rem = tile, e = -1, mt_e = 1, cnt_e = 0;
#pragma unroll
    for (int ee = 0; ee < NE; ee++) {
        int c = g_cnt[ee];
        int mt = (c + BM - 1) / BM;
        int te = mt * NT;
        if (e < 0) {
            if (rem < te) { e = ee; mt_e = mt; cnt_e = c; }
            else rem -= te;
        }
    }
    e_o = e;
    cnt_o = cnt_e;
    mb_o = (rem % mt_e) * BM;
    nb_idx_o = rem / mt_e;
}

// ---------------- small kernels ------------------------------------------------
__global__ void zero_cnt_kernel() {
    if (threadIdx.x < NE) g_cnt[threadIdx.x] = 0;
}

// fused fp32->fp16 + transpose for all 3 weight tensors.
// z: 0..NE-1 -> wg[H][I]->wgT[I][H], NE..2NE-1 -> wu, 2NE..3NE-1 -> wd[I][H]->wdT[H][I]
__global__ void conv_transpose_kernel(const float* __restrict__ wg,
                                      const float* __restrict__ wu,
                                      const float* __restrict__ wd) {
    __shared__ float t[32][33];
    int zz = blockIdx.z;
    int which = zz / NE, e = zz % NE;
    const float* in;
    __half* out;
    int R, C;
    if (which == 0)      { in = wg + (size_t)e * HD * ID; out = g_wgT + (size_t)e * ID * HD; R = HD; C = ID; }
    else if (which == 1) { in = wu + (size_t)e * HD * ID; out = g_wuT + (size_t)e * ID * HD; R = HD; C = ID; }
    else                 { in = wd + (size_t)e * ID * HD; out = g_wdT + (size_t)e * HD * ID; R = ID; C = HD; }
    int c0 = blockIdx.x * 32, r0 = blockIdx.y * 32;
    if (c0 >= C || r0 >= R) return;
    int tx = threadIdx.x, ty = threadIdx.y;
#pragma unroll
    for (int i = 0; i < 4; i++)
        t[ty + i * 8][tx] = in[(size_t)(r0 + ty + i * 8) * C + c0 + tx];
    __syncthreads();
#pragma unroll
    for (int i = 0; i < 4; i++)
        out[(size_t)(c0 + ty + i * 8) * R + r0 + tx] = __float2half_rn(t[tx][ty + i * 8]);
}

// Router + fused fp16 conversion of x. One warp per token.
__global__ void router_kernel(const float* __restrict__ x, const float* __restrict__ gw) {
    extern __shared__ float s_gw[];  // NE*HD = 64 KB
    for (int i = threadIdx.x; i < NE * HD; i += blockDim.x) s_gw[i] = gw[i];
    __syncthreads();

    int gtid = blockIdx.x * blockDim.x + threadIdx.x;
    int t = gtid >> 5, lane = gtid & 31;
    if (t >= TOK) return;

    float acc[NE];
#pragma unroll
    for (int e = 0; e < NE; e++) acc[e] = 0.f;

    const float* xr = x + (size_t)t * HD;
    __half* xo = g_xh + (size_t)t * HD;
    for (int i = lane; i < HD; i += 32) {
        float xv = xr[i];
        xo[i] = __float2half_rn(xv);
#pragma unroll
        for (int e = 0; e < NE; e++) acc[e] += xv * s_gw[e * HD + i];
    }
#pragma unroll
    for (int e = 0; e < NE; e++) {
#pragma unroll
        for (int off = 16; off > 0; off >>= 1)
            acc[e] += __shfl_xor_sync(0xffffffffu, acc[e], off);
    }
    if (lane == 0) {
        int i0 = 0; float l0 = acc[0];
#pragma unroll
        for (int e = 1; e < NE; e++) if (acc[e] > l0) { l0 = acc[e]; i0 = e; }
        int i1 = -1; float l1 = -1e30f;
#pragma unroll
        for (int e = 0; e < NE; e++) if (e != i0 && acc[e] > l1) { l1 = acc[e]; i1 = e; }
        float ex = __expf(l1 - l0);
        float w0 = 1.f / (1.f + ex);
        float w1 = ex * w0;
        g_w2[2 * t] = w0;
        g_w2[2 * t + 1] = w1;
        int s0 = atomicAdd(&g_cnt[i0], 1);
        g_tokp[i0 * TOK + s0] = t;                          // k = 0
        int s1 = atomicAdd(&g_cnt[i1], 1);
        g_tokp[i1 * TOK + s1] = t | 0x80000000;             // k = 1
    }
}

// ---------------- GEMM1: persistent warp-specialized, no trans-LDSM -------------
struct SmemG1 {
    __half A[NSTG][BM][A_ST];      // 73728 B
    __half Bg[NSTG][BN1][B_ST];    // 73728 B  ([n][k] rows)
    __half Bu[NSTG][BN1][B_ST];    // 73728 B
};                                 // 221184 B

__device__ __forceinline__ void g1_load(SmemG1* s, int st, int k0, const int* tok8,
                                        int e, int n_base, int ptid) {
#pragma unroll
    for (int i = 0; i < 8; i++) {                 // A: 128 rows x 8 chunks = 1024
        int idx = ptid + i * 128;
        int row = idx >> 3, c = idx & 7;
        cp16(saddr(&s->A[st][row][c * 8]), &g_xh[(size_t)tok8[i] * HD + k0 + c * 8]);
    }
    const __half* bg = g_wgT + ((size_t)e * ID + n_base) * HD + k0;
    const __half* bu = g_wuT + ((size_t)e * ID + n_base) * HD + k0;
#pragma unroll
    for (int i = 0; i < 8; i++) {                 // Bg/Bu: 128 n-rows x 8 chunks
        int idx = ptid + i * 128;
        int row = idx >> 3, c = idx & 7;
        cp16(saddr(&s->Bg[st][row][c * 8]), bg + (size_t)row * HD + c * 8);
        cp16(saddr(&s->Bu[st][row][c * 8]), bu + (size_t)row * HD + c * 8);
    }
}

__global__ void __launch_bounds__(NTHR) gemm1_kernel() {
    extern __shared__ __align__(16) char smem_raw[];
    SmemG1* s = (SmemG1*)smem_raw;
    int tid = threadIdx.x;
    const int T = total_tiles(NT1);

    if (tid >= 256) {
        // ---------------- producer (4 warps) ----------------
        int ptid = tid - 256;
        int base_row = ptid >> 3;
        int g = 0;
        for (int tile = blockIdx.x; tile < T; tile += gridDim.x) {
            int e, m_base, n_idx, cnt;
            decode_tile(tile, NT1, e, m_base, n_idx, cnt);
            int n_base = n_idx * BN1;
            int tok8[8];
#pragma unroll
            for (int i = 0; i < 8; i++) {
                int m = m_base + base_row + 16 * i;
                tok8[i] = (m < cnt) ? (g_tokp[e * TOK + m] & 0x7fffffff) : 0;
            }
            for (int kt = 0; kt < KT1; kt++) {
                int sg = g & 3;
                if (g >= NSTG) bar_sync(5 + sg);               // EMPTY
                g1_load(s, sg, kt * BK, tok8, e, n_base, ptid);
                cp_commit();
                if (g >= 1) { cp_wait<1>(); bar_arrive(1 + ((g - 1) & 3)); }  // FULL
                g++;
            }
        }
        if (g >= 1) { cp_wait<0>(); bar_arrive(1 + ((g - 1) & 3)); }
        return;
    }

    // ---------------- consumer (8 warps) ----------------
    int wid = tid >> 5, lane = tid & 31;
    int wm = wid >> 2, wn = wid & 3;               // 2 x 4 warps, warp 64x32
    int r = lane >> 2, cq = lane & 3;
    int lrow = lane & 15, lcol = (lane >> 4) << 3;
    // B (non-trans x4 on [n][k]): lanes 0-7 n-rows 0-7 k0, 8-15 rows 0-7 k+8,
    // 16-23 rows 8-15 k0, 24-31 rows 8-15 k+8
    int brow = (lane & 7) + ((lane >> 4) << 3);
    int bkof = ((lane >> 3) & 1) << 3;
    int g = 0;

    for (int tile = blockIdx.x; tile < T; tile += gridDim.x) {
        int e, m_base, n_idx, cnt;
        decode_tile(tile, NT1, e, m_base, n_idx, cnt);
        int n_base = n_idx * BN1;

        float acc_g[4][4][4], acc_u[4][4][4];
#pragma unroll
        for (int mf = 0; mf < 4; mf++)
#pragma unroll
            for (int nf = 0; nf < 4; nf++)
#pragma unroll
                for (int k = 0; k < 4; k++) { acc_g[mf][nf][k] = 0.f; acc_u[mf][nf][k] = 0.f; }

        for (int kt = 0; kt < KT1; kt++) {
            int sg = g & 3;
            bar_sync(1 + sg);                                 // FULL
            uint32_t sA  = saddr(&s->A[sg][0][0]);
            uint32_t sBg = saddr(&s->Bg[sg][0][0]);
            uint32_t sBu = saddr(&s->Bu[sg][0][0]);
#pragma unroll
            for (int ks = 0; ks < BK / 16; ks++) {
                int k16 = ks * 16;
                uint32_t a[4][4];
#pragma unroll
                for (int mf = 0; mf < 4; mf++)
                    ldsm_x4(a[mf], sA + 2 * ((wm * 64 + mf * 16 + lrow) * A_ST + k16 + lcol));
                uint32_t bg[2][4], bu[2][4];
#pragma unroll
                for (int ng = 0; ng < 2; ng++) {
                    uint32_t off = 2 * ((wn * 32 + ng * 16 + brow) * B_ST + k16 + bkof);
                    ldsm_x4(bg[ng], sBg + off);
                    ldsm_x4(bu[ng], sBu + off);
                }
#pragma unroll
                for (int mf = 0; mf < 4; mf++)
#pragma unroll
                    for (int nf = 0; nf < 4; nf++) {
                        mma_f16(acc_g[mf][nf], a[mf], &bg[nf >> 1][(nf & 1) * 2]);
                        mma_f16(acc_u[mf][nf], a[mf], &bu[nf >> 1][(nf & 1) * 2]);
                    }
            }
            bar_arrive(5 + sg);                               // EMPTY
            g++;
        }

        // epilogue: silu(g)*u -> fp16 -> g_hh
#pragma unroll
        for (int mf = 0; mf < 4; mf++) {
#pragma unroll
            for (int nf = 0; nf < 4; nf++) {
                int rl = wm * 64 + mf * 16 + r;
                int col = n_base + wn * 32 + nf * 8 + cq * 2;
                if (m_base + rl < cnt) {
                    float g0 = acc_g[mf][nf][0], u0 = acc_u[mf][nf][0];
                    float g1 = acc_g[mf][nf][1], u1 = acc_u[mf][nf][1];
                    float v0 = (g0 / (1.f + __expf(-g0))) * u0;
                    float v1 = (g1 / (1.f + __expf(-g1))) * u1;
                    __half2* p = (__half2*)&g_hh[((size_t)e * TOK + m_base + rl) * ID + col];
                    *p = __floats2half2_rn(v0, v1);
                }
                if (m_base + rl + 8 < cnt) {
                    float g0 = acc_g[mf][nf][2], u0 = acc_u[mf][nf][2];
                    float g1 = acc_g[mf][nf][3], u1 = acc_u[mf][nf][3];
                    float v0 = (g0 / (1.f + __expf(-g0))) * u0;
                    float v1 = (g1 / (1.f + __expf(-g1))) * u1;
                    __half2* p = (__half2*)&g_hh[((size_t)e * TOK + m_base + rl + 8) * ID + col];
                    *p = __floats2half2_rn(v0, v1);
                }
            }
        }
    }
}

// ---------------- GEMM2: persistent warp-specialized, no trans-LDSM -------------
struct SmemG2 {
    __half A[NSTG][BM][A_ST];      // 73728 B
    __half B[NSTG][BN2][B_ST];     // 147456 B  ([n][k] rows)
};                                 // 221184 B

__device__ __forceinline__ void g2_load(SmemG2* s, int st, int k0,
                                        int e, int m_base, int n_base, int ptid) {
    const __half* arow = g_hh + ((size_t)e * TOK + m_base) * ID + k0;
    const __half* brow = g_wdT + ((size_t)e * HD + n_base) * ID + k0;
#pragma unroll
    for (int i = 0; i < 8; i++) {                 // A: 1024 chunks
        int idx = ptid + i * 128;
        int row = idx >> 3, c = idx & 7;
        cp16(saddr(&s->A[st][row][c * 8]), arow + (size_t)row * ID + c * 8);
    }
#pragma unroll
    for (int i = 0; i < 16; i++) {                // B: 256 n-rows x 8 chunks = 2048
        int idx = ptid + i * 128;
        int row = idx >> 3, c = idx & 7;
        cp16(saddr(&s->B[st][row][c * 8]), brow + (size_t)row * ID + c * 8);
    }
}

__global__ void __launch_bounds__(NTHR) gemm2_kernel() {
    extern __shared__ __align__(16) char smem_raw[];
    SmemG2* s = (SmemG2*)smem_raw;
    int tid = threadIdx.x;
    const int T = total_tiles(NT2);

    if (tid >= 256) {
        // ---------------- producer (4 warps) ----------------
        int ptid = tid - 256;
        int g = 0;
        for (int tile = blockIdx.x; tile < T; tile += gridDim.x) {
            int e, m_base, n_idx, cnt;
            decode_tile(tile, NT2, e, m_base, n_idx, cnt);
            int n_base = n_idx * BN2;
            for (int kt = 0; kt < KT2; kt++) {
                int sg = g & 3;
                if (g >= NSTG) bar_sync(5 + sg);               // EMPTY
                g2_load(s, sg, kt * BK, e, m_base, n_base, ptid);
                cp_commit();
                if (g >= 1) { cp_wait<1>(); bar_arrive(1 + ((g - 1) & 3)); }  // FULL
                g++;
            }
        }
        if (g >= 1) { cp_wait<0>(); bar_arrive(1 + ((g - 1) & 3)); }
        return;
    }

    // ---------------- consumer (8 warps) ----------------
    int wid = tid >> 5, lane = tid & 31;
    int wm = wid >> 2, wn = wid & 3;               // 2 x 4 warps, warp 64x64
    int r = lane >> 2, cq = lane & 3;
    int lrow = lane & 15, lcol = (lane >> 4) << 3;
    int brow = (lane & 7) + ((lane >> 4) << 3);
    int bkof = ((lane >> 3) & 1) << 3;
    int g = 0;

    for (int tile = blockIdx.x; tile < T; tile += gridDim.x) {
        int e, m_base, n_idx, cnt;
        decode_tile(tile, NT2, e, m_base, n_idx, cnt);
        int n_base = n_idx * BN2;

        float acc[4][8][4];
#pragma unroll
        for (int mf = 0; mf < 4; mf++)
#pragma unroll
            for (int nf = 0; nf < 8; nf++)
#pragma unroll
                for (int k = 0; k < 4; k++) acc[mf][nf][k] = 0.f;

        for (int kt = 0; kt < KT2; kt++) {
            int sg = g & 3;
            bar_sync(1 + sg);                                 // FULL
            uint32_t sA = saddr(&s->A[sg][0][0]);
            uint32_t sB = saddr(&s->B[sg][0][0]);
#pragma unroll
            for (int ks = 0; ks < BK / 16; ks++) {
                int k16 = ks * 16;
                uint32_t a[4][4];
#pragma unroll
                for (int mf = 0; mf < 4; mf++)
                    ldsm_x4(a[mf], sA + 2 * ((wm * 64 + mf * 16 + lrow) * A_ST + k16 + lcol));
                uint32_t b[4][4];
#pragma unroll
                for (int ng = 0; ng < 4; ng++) {
                    uint32_t off = 2 * ((wn * 64 + ng * 16 + brow) * B_ST + k16 + bkof);
                    ldsm_x4(b[ng], sB + off);
                }
#pragma unroll
                for (int mf = 0; mf < 4; mf++)
#pragma unroll
                    for (int nf = 0; nf < 8; nf++)
                        mma_f16(acc[mf][nf], a[mf], &b[nf >> 1][(nf & 1) * 2]);
            }
            bar_arrive(5 + sg);                               // EMPTY
            g++;
        }

        // epilogue: plain stores to g_y[k][t]
#pragma unroll
        for (int mf = 0; mf < 4; mf++) {
            int rl0 = wm * 64 + mf * 16 + r;
            int pk0 = (m_base + rl0 < cnt) ? g_tokp[e * TOK + m_base + rl0] : -1;
            int pk1 = (m_base + rl0 + 8 < cnt) ? g_tokp[e * TOK + m_base + rl0 + 8] : -1;
#pragma unroll
            for (int nf = 0; nf < 8; nf++) {
                int col = n_base + wn * 64 + nf * 8 + cq * 2;
                if (pk0 != -1) {
                    int t = pk0 & 0x7fffffff;
                    int k = (uint32_t)pk0 >> 31;
                    float2* p = (float2*)&g_y[((size_t)k * TOK + t) * HD + col];
                    *p = make_float2(acc[mf][nf][0], acc[mf][nf][1]);
                }
                if (pk1 != -1) {
                    int t = pk1 & 0x7fffffff;
                    int k = (uint32_t)pk1 >> 31;
                    float2* p = (float2*)&g_y[((size_t)k * TOK + t) * HD + col];
                    *p = make_float2(acc[mf][nf][2], acc[mf][nf][3]);
                }
            }
        }
    }
}

// ---------------- combine: out = w0*y0 + w1*y1 ----------------------------------
__global__ void combine_kernel(float4* __restrict__ out) {
    const int n4 = TOK * HD / 4;
    const float4* y0 = (const float4*)g_y;
    const float4* y1 = y0 + n4;
    for (int i = blockIdx.x * blockDim.x + threadIdx.x; i < n4; i += gridDim.x * blockDim.x) {
        int t = i / (HD / 4);
        float w0 = g_w2[2 * t], w1 = g_w2[2 * t + 1];
        float4 a = y0[i], b = y1[i];
        float4 o;
        o.x = w0 * a.x + w1 * b.x;
        o.y = w0 * a.y + w1 * b.y;
        o.z = w0 * a.z + w1 * b.z;
        o.w = w0 * a.w + w1 * b.w;
        out[i] = o;
    }
}

// ---------------- host launcher -------------------------------------------------
extern "C" void kernel_launch(void* const* d_in, const int* in_sizes, int n_in,
                              void* d_out, int out_size) {
    const float* x  = (const float*)d_in[0];
    const float* gw = (const float*)d_in[1];
    const float* wg = (const float*)d_in[2];
    const float* wu = (const float*)d_in[3];
    const float* wd = (const float*)d_in[4];
    (void)in_sizes; (void)n_in; (void)out_size;

    int nsm = 148;
    cudaDeviceGetAttribute(&nsm, cudaDevAttrMultiProcessorCount, 0);

    zero_cnt_kernel<<<1, 32>>>();

    {
        dim3 grid(64, 64, 3 * NE);
        dim3 blk(32, 8, 1);
        conv_transpose_kernel<<<grid, blk>>>(wg, wu, wd);
    }

    cudaFuncSetAttribute(router_kernel, cudaFuncAttributeMaxDynamicSharedMemorySize,
                         NE * HD * (int)sizeof(float));
    router_kernel<<<TOK * 32 / 256, 256, NE * HD * sizeof(float)>>>(x, gw);

    cudaFuncSetAttribute(gemm1_kernel, cudaFuncAttributeMaxDynamicSharedMemorySize,
                         (int)sizeof(SmemG1));
    gemm1_kernel<<<nsm, NTHR, sizeof(SmemG1)>>>();

    cudaFuncSetAttribute(gemm2_kernel, cudaFuncAttributeMaxDynamicSharedMemorySize,
                         (int)sizeof(SmemG2));
    gemm2_kernel<<<nsm, NTHR, sizeof(SmemG2)>>>();

    combine_kernel<<<2048, 256>>>((float4*)d_out);
}

// round 12
// speedup vs baseline: 1.0649x; 1.0649x over previous
#include <cuda_runtime.h>
#include <cuda_fp16.h>
#include <cstdint>

#define TOK 8192
#define HD  2048
#define ID  1408
#define NE  8

#define BM   128
#define BK   64
#define BN1  64
#define BN2  128
#define NTHR 256
#define KT1  (HD / BK)    // 32
#define KT2  (ID / BK)    // 22
#define A_ST 72           // 64 + 8 halves -> 144B row stride
#define B1_ST 72          // 64 + 8 halves ([k][n], n=64)
#define B2_ST 136         // 128 + 8 halves ([k][n], n=128)

// ---------------- device scratch (no allocations allowed) ----------------------
__device__ __half g_xh[(size_t)TOK * HD];       // fp16 x
__device__ __half g_wgh[(size_t)NE * HD * ID];  // fp16 weights, native [k][n]
__device__ __half g_wuh[(size_t)NE * HD * ID];
__device__ __half g_wdh[(size_t)NE * ID * HD];
__device__ int    g_cnt[NE];
__device__ int    g_tokp[NE * TOK];             // token | (k<<31)
__device__ float  g_w2[TOK * 2];                // per-token (w0, w1)
__device__ __half g_hh[(size_t)NE * TOK * ID];  // fp16 intermediate (slot-indexed)
__device__ float  g_y[(size_t)2 * TOK * HD];    // unweighted expert outputs per k

// ---------------- helpers ------------------------------------------------------
__device__ __forceinline__ uint32_t saddr(const void* p) {
    return (uint32_t)__cvta_generic_to_shared(p);
}
__device__ __forceinline__ void cp16(uint32_t dst, const void* src) {
    asm volatile("cp.async.cg.shared.global [%0], [%1], 16;" :: "r"(dst), "l"(src));
}
__device__ __forceinline__ void cp_commit() { asm volatile("cp.async.commit_group;"); }
template <int N>
__device__ __forceinline__ void cp_wait() { asm volatile("cp.async.wait_group %0;" :: "n"(N)); }

__device__ __forceinline__ void ldsm_x4(uint32_t* r, uint32_t addr) {
    asm volatile("ldmatrix.sync.aligned.m8n8.x4.shared.b16 {%0,%1,%2,%3}, [%4];"
                 : "=r"(r[0]), "=r"(r[1]), "=r"(r[2]), "=r"(r[3]) : "r"(addr));
}
__device__ __forceinline__ void ldsm_x4t(uint32_t* r, uint32_t addr) {
    asm volatile("ldmatrix.sync.aligned.m8n8.x4.trans.shared.b16 {%0,%1,%2,%3}, [%4];"
                 : "=r"(r[0]), "=r"(r[1]), "=r"(r[2]), "=r"(r[3]) : "r"(addr));
}
__device__ __forceinline__ void mma_f16(float d[4], const uint32_t a[4], const uint32_t b[2]) {
    asm volatile(
        "mma.sync.aligned.m16n8k16.row.col.f32.f16.f16.f32 "
        "{%0,%1,%2,%3}, {%4,%5,%6,%7}, {%8,%9}, {%0,%1,%2,%3};"
        : "+f"(d[0]), "+f"(d[1]), "+f"(d[2]), "+f"(d[3])
        : "r"(a[0]), "r"(a[1]), "r"(a[2]), "r"(a[3]), "r"(b[0]), "r"(b[1]));
}

// ---------------- small kernels ------------------------------------------------
__global__ void zero_cnt_kernel() {
    if (threadIdx.x < NE) g_cnt[threadIdx.x] = 0;
}

// single conv pass for all 3 weight tensors (blockIdx.z selects), no transpose
__global__ void conv_half_kernel(const float4* __restrict__ wg,
                                 const float4* __restrict__ wu,
                                 const float4* __restrict__ wd) {
    const int n4 = NE * HD * ID / 4;
    const float4* in = blockIdx.z == 0 ? wg : blockIdx.z == 1 ? wu : wd;
    uint2* out = (uint2*)(blockIdx.z == 0 ? g_wgh : blockIdx.z == 1 ? g_wuh : g_wdh);
    for (int i = blockIdx.x * blockDim.x + threadIdx.x; i < n4; i += gridDim.x * blockDim.x) {
        float4 v = in[i];
        __half2 lo = __floats2half2_rn(v.x, v.y);
        __half2 hi = __floats2half2_rn(v.z, v.w);
        uint2 o;
        o.x = *(uint32_t*)&lo;
        o.y = *(uint32_t*)&hi;
        out[i] = o;
    }
}

// Router + fused fp16 conversion of x. One warp per token.
__global__ void router_kernel(const float* __restrict__ x, const float* __restrict__ gw) {
    extern __shared__ float s_gw[];  // NE*HD = 64 KB
    for (int i = threadIdx.x; i < NE * HD; i += blockDim.x) s_gw[i] = gw[i];
    __syncthreads();

    int gtid = blockIdx.x * blockDim.x + threadIdx.x;
    int t = gtid >> 5, lane = gtid & 31;
    if (t >= TOK) return;

    float acc[NE];
#pragma unroll
    for (int e = 0; e < NE; e++) acc[e] = 0.f;

    const float* xr = x + (size_t)t * HD;
    __half* xo = g_xh + (size_t)t * HD;
    for (int i = lane; i < HD; i += 32) {
        float xv = xr[i];
        xo[i] = __float2half_rn(xv);
#pragma unroll
        for (int e = 0; e < NE; e++) acc[e] += xv * s_gw[e * HD + i];
    }
#pragma unroll
    for (int e = 0; e < NE; e++) {
#pragma unroll
        for (int off = 16; off > 0; off >>= 1)
            acc[e] += __shfl_xor_sync(0xffffffffu, acc[e], off);
    }
    if (lane == 0) {
        int i0 = 0; float l0 = acc[0];
#pragma unroll
        for (int e = 1; e < NE; e++) if (acc[e] > l0) { l0 = acc[e]; i0 = e; }
        int i1 = -1; float l1 = -1e30f;
#pragma unroll
        for (int e = 0; e < NE; e++) if (e != i0 && acc[e] > l1) { l1 = acc[e]; i1 = e; }
        float ex = __expf(l1 - l0);
        float w0 = 1.f / (1.f + ex);
        float w1 = ex * w0;
        g_w2[2 * t] = w0;
        g_w2[2 * t + 1] = w1;
        int s0 = atomicAdd(&g_cnt[i0], 1);
        g_tokp[i0 * TOK + s0] = t;                          // k = 0
        int s1 = atomicAdd(&g_cnt[i1], 1);
        g_tokp[i1 * TOK + s1] = t | 0x80000000;             // k = 1
    }
}

// ---------------- GEMM1: h = silu(x@Wg)*(x@Wu); 128x64x64, 2 CTAs/SM ------------
// 8 warps as 4(m) x 2(n); warp tile 32x32 for BOTH g and u -> 64 acc regs.
struct SmemG1 {
    __half A[3][BM][A_ST];      // 55296 B
    __half Bg[3][BK][B1_ST];    // 27648 B
    __half Bu[3][BK][B1_ST];    // 27648 B
    int    tok[BM];             // 512 B
};                              // ~111 KB -> 2 CTAs/SM

__device__ __forceinline__ void g1_load(SmemG1* s, int st, int k0,
                                        int e, int n_base, int tid) {
#pragma unroll
    for (int i = 0; i < 4; i++) {                 // A: 128 rows x 8 chunks = 1024
        int idx = tid + i * NTHR;
        int row = idx >> 3, c = idx & 7;
        cp16(saddr(&s->A[st][row][c * 8]),
             &g_xh[(size_t)s->tok[row] * HD + k0 + c * 8]);
    }
    const __half* bg = g_wgh + ((size_t)e * HD + k0) * ID + n_base;
    const __half* bu = g_wuh + ((size_t)e * HD + k0) * ID + n_base;
#pragma unroll
    for (int i = 0; i < 2; i++) {                 // Bg/Bu: 64 k-rows x 8 chunks
        int idx = tid + i * NTHR;
        int kr = idx >> 3, c = idx & 7;
        cp16(saddr(&s->Bg[st][kr][c * 8]), bg + (size_t)kr * ID + c * 8);
        cp16(saddr(&s->Bu[st][kr][c * 8]), bu + (size_t)kr * ID + c * 8);
    }
}

__global__ void __launch_bounds__(NTHR, 2) gemm1_kernel() {
    extern __shared__ __align__(16) char smem_raw[];
    SmemG1* s = (SmemG1*)smem_raw;

    int e = blockIdx.z;
    int cnt = g_cnt[e];
    int m_base = blockIdx.y * BM;
    if (m_base >= cnt) return;
    int n_base = blockIdx.x * BN1;
    int tid = threadIdx.x;

    if (tid < BM) {
        int m = m_base + tid;
        s->tok[tid] = (m < cnt) ? (g_tokp[e * TOK + m] & 0x7fffffff) : 0;
    }
    __syncthreads();

    int wid = tid >> 5, lane = tid & 31;
    int wm = wid >> 1, wn = wid & 1;               // 4 x 2 warps, warp 32x32
    int r = lane >> 2, cq = lane & 3;
    int lrow = lane & 15, lcol = (lane >> 4) << 3;

    float acc_g[2][4][4], acc_u[2][4][4];
#pragma unroll
    for (int mf = 0; mf < 2; mf++)
#pragma unroll
        for (int nf = 0; nf < 4; nf++)
#pragma unroll
            for (int k = 0; k < 4; k++) { acc_g[mf][nf][k] = 0.f; acc_u[mf][nf][k] = 0.f; }

    g1_load(s, 0, 0, e, n_base, tid);  cp_commit();
    g1_load(s, 1, BK, e, n_base, tid); cp_commit();

    for (int kt = 0; kt < KT1; kt++) {
        cp_wait<1>();
        __syncthreads();
        int nxt = kt + 2;
        if (nxt < KT1) g1_load(s, nxt % 3, nxt * BK, e, n_base, tid);
        cp_commit();

        int sg = kt % 3;
        uint32_t sA  = saddr(&s->A[sg][0][0]);
        uint32_t sBg = saddr(&s->Bg[sg][0][0]);
        uint32_t sBu = saddr(&s->Bu[sg][0][0]);
#pragma unroll
        for (int ks = 0; ks < BK / 16; ks++) {
            int k16 = ks * 16;
            uint32_t a[2][4];
#pragma unroll
            for (int mf = 0; mf < 2; mf++)
                ldsm_x4(a[mf], sA + 2 * ((wm * 32 + mf * 16 + lrow) * A_ST + k16 + lcol));
            uint32_t bg[2][4], bu[2][4];
#pragma unroll
            for (int ng = 0; ng < 2; ng++) {
                uint32_t off = 2 * ((k16 + lrow) * B1_ST + wn * 32 + ng * 16 + lcol);
                ldsm_x4t(bg[ng], sBg + off);
                ldsm_x4t(bu[ng], sBu + off);
            }
#pragma unroll
            for (int mf = 0; mf < 2; mf++)
#pragma unroll
                for (int nf = 0; nf < 4; nf++) {
                    mma_f16(acc_g[mf][nf], a[mf], &bg[nf >> 1][(nf & 1) * 2]);
                    mma_f16(acc_u[mf][nf], a[mf], &bu[nf >> 1][(nf & 1) * 2]);
                }
        }
    }

    // epilogue: silu(g)*u -> fp16 -> g_hh
#pragma unroll
    for (int mf = 0; mf < 2; mf++) {
#pragma unroll
        for (int nf = 0; nf < 4; nf++) {
            int rl = wm * 32 + mf * 16 + r;
            int col = n_base + wn * 32 + nf * 8 + cq * 2;
            if (m_base + rl < cnt) {
                float g0 = acc_g[mf][nf][0], u0 = acc_u[mf][nf][0];
                float g1 = acc_g[mf][nf][1], u1 = acc_u[mf][nf][1];
                float v0 = (g0 / (1.f + __expf(-g0))) * u0;
                float v1 = (g1 / (1.f + __expf(-g1))) * u1;
                __half2* p = (__half2*)&g_hh[((size_t)e * TOK + m_base + rl) * ID + col];
                *p = __floats2half2_rn(v0, v1);
            }
            if (m_base + rl + 8 < cnt) {
                float g0 = acc_g[mf][nf][2], u0 = acc_u[mf][nf][2];
                float g1 = acc_g[mf][nf][3], u1 = acc_u[mf][nf][3];
                float v0 = (g0 / (1.f + __expf(-g0))) * u0;
                float v1 = (g1 / (1.f + __expf(-g1))) * u1;
                __half2* p = (__half2*)&g_hh[((size_t)e * TOK + m_base + rl + 8) * ID + col];
                *p = __floats2half2_rn(v0, v1);
            }
        }
    }
}

// ---------------- GEMM2: y = h @ Wd; 128x128x64, 2 CTAs/SM ----------------------
// 8 warps as 4(m) x 2(n); warp tile 32x64 -> 64 acc regs.
struct SmemG2 {
    __half A[3][BM][A_ST];      // 55296 B
    __half B[3][BK][B2_ST];     // 52224 B
};                              // ~105 KB -> 2 CTAs/SM

__device__ __forceinline__ void g2_load(SmemG2* s, int st, int k0,
                                        int e, int m_base, int n_base, int tid) {
    const __half* arow = g_hh + ((size_t)e * TOK + m_base) * ID + k0;
    const __half* brow = g_wdh + ((size_t)e * ID + k0) * HD + n_base;
#pragma unroll
    for (int i = 0; i < 4; i++) {                 // A: 1024 chunks
        int idx = tid + i * NTHR;
        int row = idx >> 3, c = idx & 7;
        cp16(saddr(&s->A[st][row][c * 8]), arow + (size_t)row * ID + c * 8);
    }
#pragma unroll
    for (int i = 0; i < 4; i++) {                 // B: 64 k-rows x 16 chunks = 1024
        int idx = tid + i * NTHR;
        int kr = idx >> 4, c = idx & 15;
        cp16(saddr(&s->B[st][kr][c * 8]), brow + (size_t)kr * HD + c * 8);
    }
}

__global__ void __launch_bounds__(NTHR, 2) gemm2_kernel() {
    extern __shared__ __align__(16) char smem_raw[];
    SmemG2* s = (SmemG2*)smem_raw;

    int e = blockIdx.z;
    int cnt = g_cnt[e];
    int m_base = blockIdx.y * BM;
    if (m_base >= cnt) return;
    int n_base = blockIdx.x * BN2;
    int tid = threadIdx.x;

    int wid = tid >> 5, lane = tid & 31;
    int wm = wid >> 1, wn = wid & 1;               // 4 x 2 warps, warp 32x64
    int r = lane >> 2, cq = lane & 3;
    int lrow = lane & 15, lcol = (lane >> 4) << 3;

    float acc[2][8][4];
#pragma unroll
    for (int mf = 0; mf < 2; mf++)
#pragma unroll
        for (int nf = 0; nf < 8; nf++)
#pragma unroll
            for (int k = 0; k < 4; k++) acc[mf][nf][k] = 0.f;

    g2_load(s, 0, 0, e, m_base, n_base, tid);  cp_commit();
    g2_load(s, 1, BK, e, m_base, n_base, tid); cp_commit();

    for (int kt = 0; kt < KT2; kt++) {
        cp_wait<1>();
        __syncthreads();
        int nxt = kt + 2;
        if (nxt < KT2) g2_load(s, nxt % 3, nxt * BK, e, m_base, n_base, tid);
        cp_commit();

        int sg = kt % 3;
        uint32_t sA = saddr(&s->A[sg][0][0]);
        uint32_t sB = saddr(&s->B[sg][0][0]);
#pragma unroll
        for (int ks = 0; ks < BK / 16; ks++) {
            int k16 = ks * 16;
            uint32_t a[2][4];
#pragma unroll
            for (int mf = 0; mf < 2; mf++)
                ldsm_x4(a[mf], sA + 2 * ((wm * 32 + mf * 16 + lrow) * A_ST + k16 + lcol));
            uint32_t b[4][4];
#pragma unroll
            for (int ng = 0; ng < 4; ng++) {
                uint32_t off = 2 * ((k16 + lrow) * B2_ST + wn * 64 + ng * 16 + lcol);
                ldsm_x4t(b[ng], sB + off);
            }
#pragma unroll
            for (int mf = 0; mf < 2; mf++)
#pragma unroll
                for (int nf = 0; nf < 8; nf++)
                    mma_f16(acc[mf][nf], a[mf], &b[nf >> 1][(nf & 1) * 2]);
        }
    }

    // epilogue: plain stores to g_y[k][t]
#pragma unroll
    for (int mf = 0; mf < 2; mf++) {
        int rl0 = wm * 32 + mf * 16 + r;
        int pk0 = (m_base + rl0 < cnt) ? g_tokp[e * TOK + m_base + rl0] : -1;
        int pk1 = (m_base + rl0 + 8 < cnt) ? g_tokp[e * TOK + m_base + rl0 + 8] : -1;
#pragma unroll
        for (int nf = 0; nf < 8; nf++) {
            int col = n_base + wn * 64 + nf * 8 + cq * 2;
            if (pk0 != -1) {
                int t = pk0 & 0x7fffffff;
                int k = (uint32_t)pk0 >> 31;
                float2* p = (float2*)&g_y[((size_t)k * TOK + t) * HD + col];
                *p = make_float2(acc[mf][nf][0], acc[mf][nf][1]);
            }
            if (pk1 != -1) {
                int t = pk1 & 0x7fffffff;
                int k = (uint32_t)pk1 >> 31;
                float2* p = (float2*)&g_y[((size_t)k * TOK + t) * HD + col];
                *p = make_float2(acc[mf][nf][2], acc[mf][nf][3]);
            }
        }
    }
}

// ---------------- combine: out = w0*y0 + w1*y1 ----------------------------------
__global__ void combine_kernel(float4* __restrict__ out) {
    const int n4 = TOK * HD / 4;
    const float4* y0 = (const float4*)g_y;
    const float4* y1 = y0 + n4;
    for (int i = blockIdx.x * blockDim.x + threadIdx.x; i < n4; i += gridDim.x * blockDim.x) {
        int t = i / (HD / 4);
        float w0 = g_w2[2 * t], w1 = g_w2[2 * t + 1];
        float4 a = y0[i], b = y1[i];
        float4 o;
        o.x = w0 * a.x + w1 * b.x;
        o.y = w0 * a.y + w1 * b.y;
        o.z = w0 * a.z + w1 * b.z;
        o.w = w0 * a.w + w1 * b.w;
        out[i] = o;
    }
}

// ---------------- host launcher -------------------------------------------------
extern "C" void kernel_launch(void* const* d_in, const int* in_sizes, int n_in,
                              void* d_out, int out_size) {
    const float* x  = (const float*)d_in[0];
    const float* gw = (const float*)d_in[1];
    const float* wg = (const float*)d_in[2];
    const float* wu = (const float*)d_in[3];
    const float* wd = (const float*)d_in[4];
    (void)in_sizes; (void)n_in; (void)out_size;

    zero_cnt_kernel<<<1, 32>>>();

    {
        dim3 grid(1024, 1, 3);
        conv_half_kernel<<<grid, 256>>>((const float4*)wg, (const float4*)wu,
                                        (const float4*)wd);
    }

    cudaFuncSetAttribute(router_kernel, cudaFuncAttributeMaxDynamicSharedMemorySize,
                         NE * HD * (int)sizeof(float));
    router_kernel<<<TOK * 32 / 256, 256, NE * HD * sizeof(float)>>>(x, gw);

    cudaFuncSetAttribute(gemm1_kernel, cudaFuncAttributeMaxDynamicSharedMemorySize,
                         (int)sizeof(SmemG1));
    dim3 grid1(ID / BN1, TOK / BM, NE);     // 22 x 64 x 8
    gemm1_kernel<<<grid1, NTHR, sizeof(SmemG1)>>>();

    cudaFuncSetAttribute(gemm2_kernel, cudaFuncAttributeMaxDynamicSharedMemorySize,
                         (int)sizeof(SmemG2));
    dim3 grid2(HD / BN2, TOK / BM, NE);     // 16 x 64 x 8
    gemm2_kernel<<<grid2, NTHR, sizeof(SmemG2)>>>();

    combine_kernel<<<2048, 256>>>((float4*)d_out);
}